// round 11
// baseline (speedup 1.0000x reference)
#include <cuda_runtime.h>
#include <cuda_bf16.h>

// ---------------- problem constants ----------------
#define CODE 2048
#define ARR  512
#define LENS 16384
#define NANG 181

// ---------------- GEMM config (mma.sync path, sm_100-safe, pure bf16) ----------------
#define K1     (2 * LENS)         // 32768 expanded K (re/im interleaved)
#define NPAD   384                // 2*181 padded
#define ZSPLIT 16
#define KCHUNK (K1 / ZSPLIT)      // 2048
#define BK     32                 // K per stage
#define NSTAGE (KCHUNK / BK)      // 64 stages
#define MT     128                // CTA M tile
#define NT     128                // CTA N tile
#define STAGEB 16384              // 128 rows x 128B = [A 64B | B 64B] per row
#define SBUF   3                  // pipeline depth (48KB static)

// ---------------- conv config ----------------
#define CONVA_BLOCKS (ARR * LENS / 256)            // 32768
#define CONVB_BLOCKS ((LENS / 32) * (NPAD / 64))   // 3072

// ---------------- sweep config ----------------
#define CPB 8
#define SWEEP_BLOCKS (CODE / CPB)   // 256

// ---------------- device scratch ----------------
__device__ __align__(16) __nv_bfloat16 g_Ah[(size_t)ARR * K1];   // 32 MB
__device__ __align__(16) __nv_bfloat16 g_Bh[(size_t)NPAD * K1];  // 24 MB
__device__ __align__(16) float g_Dp[ZSPLIT][ARR * NPAD];         // 12.5 MB split-K partials
__device__ __align__(16) float g_Dfull[ARR * NPAD];
__device__ float g_P[SWEEP_BLOCKS];
__device__ float g_D[SWEEP_BLOCKS];
__device__ int   g_ctr = 0;        // last-block counter (winner resets -> replay-safe)

typedef unsigned long long u64;
typedef unsigned int u32;

// ---------------- PTX helpers ----------------
__device__ __forceinline__ u64 pk2(float lo, float hi) {
    u64 r;
    asm("mov.b64 %0, {%1, %2};" : "=l"(r) : "f"(lo), "f"(hi));
    return r;
}
__device__ __forceinline__ u64 ffma2(u64 a, u64 b, u64 c) {
    u64 d;
    asm("fma.rn.f32x2 %0, %1, %2, %3;" : "=l"(d) : "l"(a), "l"(b), "l"(c));
    return d;
}
__device__ __forceinline__ float2 unpk2(u64 v) {
    float lo, hi;
    asm("mov.b64 {%0, %1}, %2;" : "=f"(lo), "=f"(hi) : "l"(v));
    return make_float2(lo, hi);
}
__device__ __forceinline__ u32 smem_u32(const void* p) {
    u32 a;
    asm("{ .reg .u64 t; cvta.to.shared.u64 t, %1; cvt.u32.u64 %0, t; }" : "=r"(a) : "l"(p));
    return a;
}

#define CP_ASYNC16(dst, src) \
    asm volatile("cp.async.cg.shared.global [%0], [%1], 16;" :: "r"(dst), "l"(src))
#define CP_COMMIT() asm volatile("cp.async.commit_group;" ::: "memory")
#define CP_WAIT1()  asm volatile("cp.async.wait_group 1;" ::: "memory")
#define CP_WAIT0()  asm volatile("cp.async.wait_group 0;" ::: "memory")

#define LDSM_X4(r, addr) \
    asm volatile("ldmatrix.sync.aligned.m8n8.x4.shared.b16 {%0,%1,%2,%3}, [%4];" \
        : "=r"((r)[0]), "=r"((r)[1]), "=r"((r)[2]), "=r"((r)[3]) : "r"(addr))

#define MMA16816(d, a, b0, b1) \
    asm volatile("mma.sync.aligned.m16n8k16.row.col.f32.bf16.bf16.f32 " \
        "{%0,%1,%2,%3}, {%4,%5,%6,%7}, {%8,%9}, {%0,%1,%2,%3};" \
        : "+f"((d)[0]), "+f"((d)[1]), "+f"((d)[2]), "+f"((d)[3]) \
        : "r"((a)[0]), "r"((a)[1]), "r"((a)[2]), "r"((a)[3]), "r"(b0), "r"(b1))

// ---------------- conv: A'' = (G * theta_n) -> bf16 (re/im interleaved), ----------------
// ----------------       B'' = steer^T expansion -> bf16 (blocks past CONVA_BLOCKS) ------
__global__ __launch_bounds__(256) void conv_kernel(
    const float* __restrict__ G_re, const float* __restrict__ G_im,
    const float* __restrict__ th_re, const float* __restrict__ th_im,
    const float* __restrict__ st_re, const float* __restrict__ st_im)
{
    __shared__ float sr[32][33], si[32][33];
    const int tid = threadIdx.x;

    if (blockIdx.x < CONVA_BLOCKS) {
        // --- convA path: one complex element per thread ---
        const int idx = blockIdx.x * 256 + tid;   // = m*LENS + k
        const int k = idx & (LENS - 1);
        float tr = th_re[k], ti = th_im[k];
        const float rn = rsqrtf(tr * tr + ti * ti);
        tr *= rn; ti *= rn;
        const float gr = G_re[idx], gi = G_im[idx];
        __nv_bfloat162 v;
        v.x = __float2bfloat16_rn(gr * tr - gi * ti);
        v.y = __float2bfloat16_rn(gr * ti + gi * tr);
        ((__nv_bfloat162*)g_Ah)[idx] = v;   // A''[m,2k], A''[m,2k+1]
        return;
    }

    // --- convB path: 32x32 steer tile -> 64 j-rows of B'' ---
    // row j=2n: (sr,-si) at (2k,2k+1); row j=2n+1: (si,sr). Rows >= 362 zero.
    const int b = blockIdx.x - CONVA_BLOCKS;
    const int k0 = (b & 511) * 32;       // LENS/32 = 512 k-tiles
    const int n0 = (b >> 9) * 32;        // 6 n-tiles

#pragma unroll
    for (int i = 0; i < 4; ++i) {
        const int id = tid + 256 * i;
        const int kk = id >> 5, nn = id & 31;
        const int n = n0 + nn;
        float vr = 0.f, vi = 0.f;
        if (n < NANG) {
            vr = st_re[(size_t)(k0 + kk) * NANG + n];
            vi = st_im[(size_t)(k0 + kk) * NANG + n];
        }
        sr[kk][nn] = vr;
        si[kk][nn] = vi;
    }
    __syncthreads();

#pragma unroll
    for (int i = 0; i < 8; ++i) {
        const int id = tid + 256 * i;          // 2048: 64 j-rows x 32 k
        const int kl = id & 31;
        const int jl = id >> 5;
        const int nl = jl >> 1;
        const bool ev = !(jl & 1);
        const float vr = sr[kl][nl], vi = si[kl][nl];
        const float c0 = ev ? vr : vi;
        const float c1 = ev ? -vi : vr;
        const size_t off2 = (size_t)(n0 * 2 + jl) * (K1 / 2) + (k0 + kl);
        __nv_bfloat162 v;
        v.x = __float2bfloat16_rn(c0);
        v.y = __float2bfloat16_rn(c1);
        ((__nv_bfloat162*)g_Bh)[off2] = v;
    }
}

// ---------------- GEMM: D = A @ B^T (bf16), split-K ----------------
// Grid (ARR/MT=4, NPAD/NT=3, ZSPLIT=16) = 192 CTAs, 256 threads (8 warps, 2M x 4N).
// Stage tile: 128 rows x 128B = [A 64B | B 64B], XOR-swizzled 16B granules.
// 3-stage cp.async pipeline, one __syncthreads per stage, BK=32 (2 k-steps of 16).
__global__ __launch_bounds__(256, 2) void gemm_mma_kernel()
{
    __shared__ __align__(128) unsigned char sT[SBUF][STAGEB];   // 48 KB

    const int tid = threadIdx.x;
    const int wid = tid >> 5;
    const int lane = tid & 31;
    const int m0 = blockIdx.x * MT;
    const int n0 = blockIdx.y * NT;
    const int bz = blockIdx.z;
    const int kc0 = bz * KCHUNK;

    const u32 smbase = smem_u32(sT);

    // ---- cp.async addressing: row r = tid>>1, 16B column cc = tid&1
    // A granules 0..3 (p=0,1), B granules 4..7 (p=2,3)
    const int r = tid >> 1;
    const int cc = tid & 1;
    u32 doff[4];
    const __nv_bfloat16* srcp[4];
#pragma unroll
    for (int p = 0; p < 4; ++p) {
        const int g = p * 2 + cc;              // 0..7 across p
        doff[p] = (u32)(r * 128 + ((g ^ (r & 7)) << 4));
        if (p < 2)
            srcp[p] = g_Ah + (size_t)(m0 + r) * K1 + kc0 + g * 8;
        else
            srcp[p] = g_Bh + (size_t)(n0 + r) * K1 + kc0 + (g - 4) * 8;
    }

    const int wm = wid >> 2;          // 0..1 -> 64 rows of M
    const int wn = wid & 3;           // 0..3 -> 32 cols of N

    float D[4][4][4];
#pragma unroll
    for (int mi = 0; mi < 4; ++mi)
#pragma unroll
        for (int ni = 0; ni < 4; ++ni)
#pragma unroll
            for (int e = 0; e < 4; ++e) D[mi][ni][e] = 0.f;

    // ---- prologue: stages 0,1
#pragma unroll
    for (int st = 0; st < 2; ++st) {
        const u32 b = smbase + st * STAGEB;
#pragma unroll
        for (int p = 0; p < 4; ++p)
            CP_ASYNC16(b + doff[p], srcp[p] + st * BK);
        CP_COMMIT();
    }

#pragma unroll 1
    for (int s = 0; s < NSTAGE; ++s) {
        if (s + 1 < NSTAGE) { CP_WAIT1(); } else { CP_WAIT0(); }
        __syncthreads();     // stage s visible; buf (s+2)%3 free to overwrite

        if (s + 2 < NSTAGE) {
            const u32 b = smbase + ((s + 2) % SBUF) * STAGEB;
#pragma unroll
            for (int p = 0; p < 4; ++p)
                CP_ASYNC16(b + doff[p], srcp[p] + (s + 2) * BK);
            CP_COMMIT();
        }

        const u32 buf = smbase + (s % SBUF) * STAGEB;

        // B fragments: [t = k-step 0,1][nc = 16-col group 0,1], pairing (r0,r2)/(r1,r3)
        u32 Bf[2][2][4];
#pragma unroll
        for (int nc = 0; nc < 2; ++nc) {
            const int row = wn * 32 + nc * 16 + (lane & 7) + ((lane >> 3) & 1) * 8;
#pragma unroll
            for (int t = 0; t < 2; ++t) {
                const u32 g = (u32)((4 + t * 2 + (lane >> 4)) ^ (row & 7));
                LDSM_X4(Bf[t][nc], buf + row * 128 + (g << 4));
            }
        }

#pragma unroll
        for (int mi = 0; mi < 4; ++mi) {
            const int row = wm * 64 + mi * 16 + (lane & 15);
            u32 Af[2][4];
#pragma unroll
            for (int t = 0; t < 2; ++t) {
                const u32 g = (u32)((t * 2 + (lane >> 4)) ^ (row & 7));
                LDSM_X4(Af[t], buf + row * 128 + (g << 4));
            }
#pragma unroll
            for (int ni = 0; ni < 4; ++ni) {
#pragma unroll
                for (int t = 0; t < 2; ++t) {
                    const u32 b0 = Bf[t][ni >> 1][ni & 1];
                    const u32 b1 = Bf[t][ni >> 1][(ni & 1) + 2];
                    MMA16816(D[mi][ni], Af[t], b0, b1);
                }
            }
        }
    }

    // ---- epilogue: write split-K partial tile (disjoint per bz -> deterministic)
    float* __restrict__ out = g_Dp[bz];
    const int rbase = m0 + wm * 64 + (lane >> 2);
    const int cbase = n0 + wn * 32 + (lane & 3) * 2;
#pragma unroll
    for (int mi = 0; mi < 4; ++mi) {
#pragma unroll
        for (int ni = 0; ni < 4; ++ni) {
            const int row = rbase + mi * 16;
            const int col = cbase + ni * 8;
            float2 v0; v0.x = D[mi][ni][0]; v0.y = D[mi][ni][1];
            float2 v1; v1.x = D[mi][ni][2]; v1.y = D[mi][ni][3];
            *(float2*)(out + (size_t)row * NPAD + col) = v0;
            *(float2*)(out + (size_t)(row + 8) * NPAD + col) = v1;
        }
    }
}

// ---------------- reduce split-K partials ----------------
__global__ __launch_bounds__(256) void reduceD_kernel()
{
    const int i = blockIdx.x * 256 + threadIdx.x;
    float s = 0.f;
#pragma unroll
    for (int z = 0; z < ZSPLIT; ++z) s += g_Dp[z][i];
    g_Dfull[i] = s;
}

// ---------------- sweep: sout = w_n @ B, fused |.|^2 + diag gather + final reduce ------
__global__ __launch_bounds__(192) void sweep_kernel(
    const float* __restrict__ w_re, const float* __restrict__ w_im,
    const int* __restrict__ sweep_angle, float* __restrict__ outp)
{
    __shared__ float2 sw[CPB * ARR];   // normalized (wr, wi), 32 KB
    __shared__ float redP[6], redD[6];
    __shared__ int s_last;

    const int tid = threadIdx.x;
    const int c0 = blockIdx.x * CPB;

    for (int idx = tid; idx < CPB * ARR; idx += 192) {
        const int ci = idx >> 9;
        const int a = idx & (ARR - 1);
        const float wr = w_re[(size_t)(c0 + ci) * ARR + a];
        const float wi = w_im[(size_t)(c0 + ci) * ARR + a];
        const float rn = rsqrtf(wr * wr + wi * wi);
        sw[idx] = make_float2(wr * rn, wi * rn);
    }
    __syncthreads();

    float sumP = 0.f, sumD = 0.f;
    const int n = tid;
    if (n < NANG) {
        const u64* __restrict__ Brow = (const u64*)g_Dfull;   // (re,im) pairs, row = NPAD/2 u64
        u64 acc[CPB];
#pragma unroll
        for (int ci = 0; ci < CPB; ++ci) acc[ci] = pk2(0.f, 0.f);

#pragma unroll 2
        for (int a = 0; a < ARR; ++a) {
            const u64 bp = Brow[(size_t)a * (NPAD / 2) + n];   // (br, bi) coalesced
            const float2 b2 = unpk2(bp);
            const u64 bq = pk2(-b2.y, b2.x);                   // (-bi, br)
#pragma unroll
            for (int ci = 0; ci < CPB; ++ci) {
                const float2 wv = sw[ci * ARR + a];
                acc[ci] = ffma2(pk2(wv.x, wv.x), bp, ffma2(pk2(wv.y, wv.y), bq, acc[ci]));
            }
        }
#pragma unroll
        for (int ci = 0; ci < CPB; ++ci) {
            const float2 s = unpk2(acc[ci]);
            const float p = s.x * s.x + s.y * s.y;
            sumP += p;
            if (sweep_angle[c0 + ci] + 90 == n) sumD += p;
        }
    }

#pragma unroll
    for (int off = 16; off > 0; off >>= 1) {
        sumP += __shfl_down_sync(0xffffffffu, sumP, off);
        sumD += __shfl_down_sync(0xffffffffu, sumD, off);
    }
    if ((tid & 31) == 0) { redP[tid >> 5] = sumP; redD[tid >> 5] = sumD; }
    __syncthreads();
    if (tid == 0) {
        float P = 0.f, Dd = 0.f;
#pragma unroll
        for (int i = 0; i < 6; ++i) { P += redP[i]; Dd += redD[i]; }
        g_P[blockIdx.x] = P;
        g_D[blockIdx.x] = Dd;
        __threadfence();
        const int prev = atomicAdd(&g_ctr, 1);
        s_last = (prev == SWEEP_BLOCKS - 1) ? 1 : 0;
    }
    __syncthreads();

    // ---- last block: deterministic final reduction (fixed order, fixed winner work)
    if (s_last) {
        __threadfence();   // acquire: make all blocks' g_P/g_D visible
        float p2 = 0.f, d2 = 0.f;
        for (int i = tid; i < SWEEP_BLOCKS; i += 192) {
            p2 += g_P[i];
            d2 += g_D[i];
        }
#pragma unroll
        for (int off = 16; off > 0; off >>= 1) {
            p2 += __shfl_down_sync(0xffffffffu, p2, off);
            d2 += __shfl_down_sync(0xffffffffu, d2, off);
        }
        if ((tid & 31) == 0) { redP[tid >> 5] = p2; redD[tid >> 5] = d2; }
        __syncthreads();
        if (tid == 0) {
            float P = 0.f, Dd = 0.f;
#pragma unroll
            for (int i = 0; i < 6; ++i) { P += redP[i]; Dd += redD[i]; }
            // -(1+K)*D + K*(S - D) = K*S - (1+2K)*D, K = 0.1
            outp[0] = 0.1f * P - 1.2f * Dd;
            g_ctr = 0;   // reset for next graph replay
        }
    }
}

// ---------------- launch ----------------
extern "C" void kernel_launch(void* const* d_in, const int* in_sizes, int n_in,
                              void* d_out, int out_size)
{
    (void)in_sizes; (void)n_in; (void)out_size;
    const float* w_re  = (const float*)d_in[0];
    const float* w_im  = (const float*)d_in[1];
    const float* th_re = (const float*)d_in[2];
    const float* th_im = (const float*)d_in[3];
    const float* G_re  = (const float*)d_in[4];
    const float* G_im  = (const float*)d_in[5];
    const float* st_re = (const float*)d_in[6];
    const float* st_im = (const float*)d_in[7];
    const int* sweep   = (const int*)d_in[10];   // addw (d_in[8],[9]) unused: var term * 0.0

    conv_kernel<<<CONVA_BLOCKS + CONVB_BLOCKS, 256>>>(G_re, G_im, th_re, th_im, st_re, st_im);
    gemm_mma_kernel<<<dim3(ARR / MT, NPAD / NT, ZSPLIT), 256>>>();
    reduceD_kernel<<<(ARR * NPAD) / 256, 256>>>();
    sweep_kernel<<<SWEEP_BLOCKS, 192>>>(w_re, w_im, sweep, (float*)d_out);
}

// round 15
// speedup vs baseline: 1.4294x; 1.4294x over previous
#include <cuda_runtime.h>
#include <cuda_bf16.h>

// ---------------- problem constants ----------------
#define CODE 2048
#define ARR  512
#define LENS 16384
#define NANG 181

// ---------------- GEMM1 config (pure bf16 mma.sync) ----------------
#define K1     (2 * LENS)         // 32768 expanded K (re/im interleaved)
#define NPAD   384                // 2*181 padded
#define ZSPLIT 32
#define KCHUNK (K1 / ZSPLIT)      // 1024
#define BK     32                 // K per stage
#define NSTAGE (KCHUNK / BK)      // 32 stages
#define MT     128
#define NT     128
#define STAGEB 16384              // 128 rows x 128B = [A 64B | B 64B]
#define SBUF   3                  // 48KB static

// ---------------- GEMM2 (sweep) config ----------------
#define K2       (2 * ARR)        // 1024
#define NSTAGE2  (K2 / BK)        // 32
#define G2_MTILES (CODE / MT)     // 16
#define G2_NTILES (NPAD / NT)     // 3
#define G2_CTAS  (G2_MTILES * G2_NTILES)   // 48

// ---------------- conv ranges ----------------
#define CONVA_BLOCKS (ARR * LENS / 256)            // 32768
#define CONVB_BLOCKS ((LENS / 32) * (NPAD / 64))   // 3072
#define CONVW_BLOCKS (CODE * ARR / 256)            // 4096

// ---------------- device scratch ----------------
__device__ __align__(16) __nv_bfloat16 g_Ah[(size_t)ARR * K1];    // 32 MB
__device__ __align__(16) __nv_bfloat16 g_Bh[(size_t)NPAD * K1];   // 24 MB
__device__ __align__(16) __nv_bfloat16 g_W[(size_t)CODE * K2];    // 4 MB
__device__ __align__(16) __nv_bfloat16 g_Bd[(size_t)NPAD * K2];   // 786 KB
__device__ __align__(16) float g_Dp[ZSPLIT][ARR * NPAD];          // 25 MB split-K partials
__device__ float g_P2[G2_CTAS];
__device__ float g_D2[G2_CTAS];

typedef unsigned long long u64;
typedef unsigned int u32;

// ---------------- PTX helpers ----------------
__device__ __forceinline__ u32 smem_u32(const void* p) {
    u32 a;
    asm("{ .reg .u64 t; cvta.to.shared.u64 t, %1; cvt.u32.u64 %0, t; }" : "=r"(a) : "l"(p));
    return a;
}

#define CP_ASYNC16(dst, src) \
    asm volatile("cp.async.cg.shared.global [%0], [%1], 16;" :: "r"(dst), "l"(src))
#define CP_COMMIT() asm volatile("cp.async.commit_group;" ::: "memory")
#define CP_WAIT1()  asm volatile("cp.async.wait_group 1;" ::: "memory")
#define CP_WAIT0()  asm volatile("cp.async.wait_group 0;" ::: "memory")

#define LDSM_X4(r, addr) \
    asm volatile("ldmatrix.sync.aligned.m8n8.x4.shared.b16 {%0,%1,%2,%3}, [%4];" \
        : "=r"((r)[0]), "=r"((r)[1]), "=r"((r)[2]), "=r"((r)[3]) : "r"(addr))

#define MMA16816(d, a, b0, b1) \
    asm volatile("mma.sync.aligned.m16n8k16.row.col.f32.bf16.bf16.f32 " \
        "{%0,%1,%2,%3}, {%4,%5,%6,%7}, {%8,%9}, {%0,%1,%2,%3};" \
        : "+f"((d)[0]), "+f"((d)[1]), "+f"((d)[2]), "+f"((d)[3]) \
        : "r"((a)[0]), "r"((a)[1]), "r"((a)[2]), "r"((a)[3]), "r"(b0), "r"(b1))

// ---------------- conv: A'' (G*theta), B'' (steer^T expand), W'' (w normalized) -> bf16 ----
__global__ __launch_bounds__(256) void conv_kernel(
    const float* __restrict__ G_re, const float* __restrict__ G_im,
    const float* __restrict__ th_re, const float* __restrict__ th_im,
    const float* __restrict__ st_re, const float* __restrict__ st_im,
    const float* __restrict__ w_re,  const float* __restrict__ w_im)
{
    __shared__ float sr[32][33], si[32][33];
    const int tid = threadIdx.x;

    if (blockIdx.x < CONVA_BLOCKS) {
        // --- A path: one complex element per thread ---
        const int idx = blockIdx.x * 256 + tid;   // = m*LENS + k
        const int k = idx & (LENS - 1);
        float tr = th_re[k], ti = th_im[k];
        const float rn = rsqrtf(tr * tr + ti * ti);
        tr *= rn; ti *= rn;
        const float gr = G_re[idx], gi = G_im[idx];
        __nv_bfloat162 v;
        v.x = __float2bfloat16_rn(gr * tr - gi * ti);
        v.y = __float2bfloat16_rn(gr * ti + gi * tr);
        ((__nv_bfloat162*)g_Ah)[idx] = v;
        return;
    }
    if (blockIdx.x >= CONVA_BLOCKS + CONVB_BLOCKS) {
        // --- W path: normalized w, interleaved (wr, wi) ---
        const int idx = (blockIdx.x - CONVA_BLOCKS - CONVB_BLOCKS) * 256 + tid;  // m*ARR + a
        const float wr = w_re[idx], wi = w_im[idx];
        const float rn = rsqrtf(wr * wr + wi * wi);
        __nv_bfloat162 v;
        v.x = __float2bfloat16_rn(wr * rn);
        v.y = __float2bfloat16_rn(wi * rn);
        ((__nv_bfloat162*)g_W)[idx] = v;
        return;
    }

    // --- B path: 32x32 steer tile -> 64 j-rows of B'' ---
    // row j=2n: (sr,-si); row j=2n+1: (si,sr). Rows >= 362 zero.
    const int b = blockIdx.x - CONVA_BLOCKS;
    const int k0 = (b & 511) * 32;       // LENS/32 = 512 k-tiles
    const int n0 = (b >> 9) * 32;        // 6 n-tiles

#pragma unroll
    for (int i = 0; i < 4; ++i) {
        const int id = tid + 256 * i;
        const int kk = id >> 5, nn = id & 31;
        const int n = n0 + nn;
        float vr = 0.f, vi = 0.f;
        if (n < NANG) {
            vr = st_re[(size_t)(k0 + kk) * NANG + n];
            vi = st_im[(size_t)(k0 + kk) * NANG + n];
        }
        sr[kk][nn] = vr;
        si[kk][nn] = vi;
    }
    __syncthreads();

#pragma unroll
    for (int i = 0; i < 8; ++i) {
        const int id = tid + 256 * i;          // 2048: 64 j-rows x 32 k
        const int kl = id & 31;
        const int jl = id >> 5;
        const int nl = jl >> 1;
        const bool ev = !(jl & 1);
        const float vr = sr[kl][nl], vi = si[kl][nl];
        const float c0 = ev ? vr : vi;
        const float c1 = ev ? -vi : vr;
        const size_t off2 = (size_t)(n0 * 2 + jl) * (K1 / 2) + (k0 + kl);
        __nv_bfloat162 v;
        v.x = __float2bfloat16_rn(c0);
        v.y = __float2bfloat16_rn(c1);
        ((__nv_bfloat162*)g_Bh)[off2] = v;
    }
}

// ---------------- GEMM1: D = A @ B^T (bf16), split-K (R10 config) ----------------
// Grid (4, 3, 32) = 384 CTAs, 256 threads (8 warps, 2M x 4N).
__global__ __launch_bounds__(256, 2) void gemm_mma_kernel()
{
    __shared__ __align__(128) unsigned char sT[SBUF][STAGEB];   // 48 KB

    const int tid = threadIdx.x;
    const int wid = tid >> 5;
    const int lane = tid & 31;
    const int m0 = blockIdx.x * MT;
    const int n0 = blockIdx.y * NT;
    const int bz = blockIdx.z;
    const int kc0 = bz * KCHUNK;

    const u32 smbase = smem_u32(sT);

    const int r = tid >> 1;
    const int cc = tid & 1;
    u32 doff[4];
    const __nv_bfloat16* srcp[4];
#pragma unroll
    for (int p = 0; p < 4; ++p) {
        const int g = p * 2 + cc;
        doff[p] = (u32)(r * 128 + ((g ^ (r & 7)) << 4));
        if (p < 2)
            srcp[p] = g_Ah + (size_t)(m0 + r) * K1 + kc0 + g * 8;
        else
            srcp[p] = g_Bh + (size_t)(n0 + r) * K1 + kc0 + (g - 4) * 8;
    }

    const int wm = wid >> 2;
    const int wn = wid & 3;

    float D[4][4][4];
#pragma unroll
    for (int mi = 0; mi < 4; ++mi)
#pragma unroll
        for (int ni = 0; ni < 4; ++ni)
#pragma unroll
            for (int e = 0; e < 4; ++e) D[mi][ni][e] = 0.f;

#pragma unroll
    for (int st = 0; st < 2; ++st) {
        const u32 b = smbase + st * STAGEB;
#pragma unroll
        for (int p = 0; p < 4; ++p)
            CP_ASYNC16(b + doff[p], srcp[p] + st * BK);
        CP_COMMIT();
    }

#pragma unroll 1
    for (int s = 0; s < NSTAGE; ++s) {
        if (s + 1 < NSTAGE) { CP_WAIT1(); } else { CP_WAIT0(); }
        __syncthreads();

        if (s + 2 < NSTAGE) {
            const u32 b = smbase + ((s + 2) % SBUF) * STAGEB;
#pragma unroll
            for (int p = 0; p < 4; ++p)
                CP_ASYNC16(b + doff[p], srcp[p] + (s + 2) * BK);
            CP_COMMIT();
        }

        const u32 buf = smbase + (s % SBUF) * STAGEB;

        u32 Bf[2][2][4];
#pragma unroll
        for (int nc = 0; nc < 2; ++nc) {
            const int row = wn * 32 + nc * 16 + (lane & 7) + ((lane >> 3) & 1) * 8;
#pragma unroll
            for (int t = 0; t < 2; ++t) {
                const u32 g = (u32)((4 + t * 2 + (lane >> 4)) ^ (row & 7));
                LDSM_X4(Bf[t][nc], buf + row * 128 + (g << 4));
            }
        }

#pragma unroll
        for (int mi = 0; mi < 4; ++mi) {
            const int row = wm * 64 + mi * 16 + (lane & 15);
            u32 Af[2][4];
#pragma unroll
            for (int t = 0; t < 2; ++t) {
                const u32 g = (u32)((t * 2 + (lane >> 4)) ^ (row & 7));
                LDSM_X4(Af[t], buf + row * 128 + (g << 4));
            }
#pragma unroll
            for (int ni = 0; ni < 4; ++ni) {
#pragma unroll
                for (int t = 0; t < 2; ++t) {
                    const u32 b0 = Bf[t][ni >> 1][ni & 1];
                    const u32 b1 = Bf[t][ni >> 1][(ni & 1) + 2];
                    MMA16816(D[mi][ni], Af[t], b0, b1);
                }
            }
        }
    }

    float* __restrict__ out = g_Dp[bz];
    const int rbase = m0 + wm * 64 + (lane >> 2);
    const int cbase = n0 + wn * 32 + (lane & 3) * 2;
#pragma unroll
    for (int mi = 0; mi < 4; ++mi) {
#pragma unroll
        for (int ni = 0; ni < 4; ++ni) {
            const int row = rbase + mi * 16;
            const int col = cbase + ni * 8;
            float2 v0; v0.x = D[mi][ni][0]; v0.y = D[mi][ni][1];
            float2 v1; v1.x = D[mi][ni][2]; v1.y = D[mi][ni][3];
            *(float2*)(out + (size_t)row * NPAD + col) = v0;
            *(float2*)(out + (size_t)(row + 8) * NPAD + col) = v1;
        }
    }
}

// ---------------- reduceBd: sum split-K partials, transpose-expand -> Bd'' bf16 --------
// Grid (ARR/32=16, NPAD/32=12), 256 threads. Bd[j][2a]=D[a][j]; [2a+1]= j even? -D[a][j+1] : D[a][j-1].
__global__ __launch_bounds__(256) void reduceBd_kernel()
{
    __shared__ float sD[32][33];
    const int tid = threadIdx.x;
    const int a0 = blockIdx.x * 32;
    const int j0 = blockIdx.y * 32;

#pragma unroll
    for (int i = 0; i < 4; ++i) {
        const int id = tid + 256 * i;
        const int al = id >> 5, jl = id & 31;
        float s = 0.f;
#pragma unroll
        for (int z = 0; z < ZSPLIT; ++z)
            s += g_Dp[z][(a0 + al) * NPAD + j0 + jl];
        sD[al][jl] = s;
    }
    __syncthreads();

#pragma unroll
    for (int i = 0; i < 4; ++i) {
        const int id = tid + 256 * i;
        const int al = id & 31, jl = id >> 5;
        const float v0 = sD[al][jl];
        const float v1 = (jl & 1) ? sD[al][jl - 1] : -sD[al][jl + 1];
        __nv_bfloat162 v;
        v.x = __float2bfloat16_rn(v0);
        v.y = __float2bfloat16_rn(v1);
        ((__nv_bfloat162*)g_Bd)[(size_t)(j0 + jl) * (K2 / 2) + a0 + al] = v;
    }
}

// ---------------- GEMM2: sout2 = W'' @ Bd''^T, fused P/D reduction epilogue ------------
// Grid (16, 3) = 48 CTAs, 256 threads. K=1024, 32 stages, no split-K.
// Epilogue scratch (sj, redP, redD) ALIASES the sT pipeline buffer (dead after mainloop).
__global__ __launch_bounds__(256, 2) void gemm2_kernel(const int* __restrict__ sweep_angle)
{
    __shared__ __align__(128) unsigned char sT[SBUF][STAGEB];   // 48 KB total (exact limit)

    const int tid = threadIdx.x;
    const int wid = tid >> 5;
    const int lane = tid & 31;
    const int m0 = blockIdx.x * MT;
    const int n0 = blockIdx.y * NT;

    const u32 smbase = smem_u32(sT);

    const int r = tid >> 1;
    const int cc = tid & 1;
    u32 doff[4];
    const __nv_bfloat16* srcp[4];
#pragma unroll
    for (int p = 0; p < 4; ++p) {
        const int g = p * 2 + cc;
        doff[p] = (u32)(r * 128 + ((g ^ (r & 7)) << 4));
        if (p < 2)
            srcp[p] = g_W + (size_t)(m0 + r) * K2 + g * 8;
        else
            srcp[p] = g_Bd + (size_t)(n0 + r) * K2 + (g - 4) * 8;
    }

    const int wm = wid >> 2;
    const int wn = wid & 3;

    float D[4][4][4];
#pragma unroll
    for (int mi = 0; mi < 4; ++mi)
#pragma unroll
        for (int ni = 0; ni < 4; ++ni)
#pragma unroll
            for (int e = 0; e < 4; ++e) D[mi][ni][e] = 0.f;

#pragma unroll
    for (int st = 0; st < 2; ++st) {
        const u32 b = smbase + st * STAGEB;
#pragma unroll
        for (int p = 0; p < 4; ++p)
            CP_ASYNC16(b + doff[p], srcp[p] + st * BK);
        CP_COMMIT();
    }

#pragma unroll 1
    for (int s = 0; s < NSTAGE2; ++s) {
        if (s + 1 < NSTAGE2) { CP_WAIT1(); } else { CP_WAIT0(); }
        __syncthreads();

        if (s + 2 < NSTAGE2) {
            const u32 b = smbase + ((s + 2) % SBUF) * STAGEB;
#pragma unroll
            for (int p = 0; p < 4; ++p)
                CP_ASYNC16(b + doff[p], srcp[p] + (s + 2) * BK);
            CP_COMMIT();
        }

        const u32 buf = smbase + (s % SBUF) * STAGEB;

        u32 Bf[2][2][4];
#pragma unroll
        for (int nc = 0; nc < 2; ++nc) {
            const int row = wn * 32 + nc * 16 + (lane & 7) + ((lane >> 3) & 1) * 8;
#pragma unroll
            for (int t = 0; t < 2; ++t) {
                const u32 g = (u32)((4 + t * 2 + (lane >> 4)) ^ (row & 7));
                LDSM_X4(Bf[t][nc], buf + row * 128 + (g << 4));
            }
        }

#pragma unroll
        for (int mi = 0; mi < 4; ++mi) {
            const int row = wm * 64 + mi * 16 + (lane & 15);
            u32 Af[2][4];
#pragma unroll
            for (int t = 0; t < 2; ++t) {
                const u32 g = (u32)((t * 2 + (lane >> 4)) ^ (row & 7));
                LDSM_X4(Af[t], buf + row * 128 + (g << 4));
            }
#pragma unroll
            for (int ni = 0; ni < 4; ++ni) {
#pragma unroll
                for (int t = 0; t < 2; ++t) {
                    const u32 b0 = Bf[t][ni >> 1][ni & 1];
                    const u32 b1 = Bf[t][ni >> 1][(ni & 1) + 2];
                    MMA16816(D[mi][ni], Af[t], b0, b1);
                }
            }
        }
    }

    // ---- epilogue scratch aliases sT (dead after mainloop) ----
    __syncthreads();   // all LDSM reads of sT complete before overwrite
    int*   sj   = (int*)&sT[0][0];          // [MT]
    float* redP = (float*)&sT[0][MT * 4];   // [8]
    float* redD = (float*)&sT[0][MT * 4 + 32];

    if (tid < MT) sj[tid] = 2 * (sweep_angle[m0 + tid] + 90);
    __syncthreads();

    // ---- fused reduction: P = sum of squares (padded cols exactly 0);
    // ---- diag: col pair (2n, 2n+1) with 2n == sj[row] -> D.
    const int rloc = wm * 64 + (lane >> 2);           // row - m0, 0..127
    const int cbase = n0 + wn * 32 + (lane & 3) * 2;  // even
    float pP = 0.f, pD = 0.f;
#pragma unroll
    for (int mi = 0; mi < 4; ++mi) {
#pragma unroll
        for (int ni = 0; ni < 4; ++ni) {
            const int col = cbase + ni * 8;
            const float d0 = D[mi][ni][0], d1 = D[mi][ni][1];
            const float d2 = D[mi][ni][2], d3 = D[mi][ni][3];
            pP += d0 * d0 + d1 * d1 + d2 * d2 + d3 * d3;
            if (sj[rloc + mi * 16] == col)     pD += d0 * d0 + d1 * d1;
            if (sj[rloc + mi * 16 + 8] == col) pD += d2 * d2 + d3 * d3;
        }
    }

#pragma unroll
    for (int off = 16; off > 0; off >>= 1) {
        pP += __shfl_down_sync(0xffffffffu, pP, off);
        pD += __shfl_down_sync(0xffffffffu, pD, off);
    }
    if (lane == 0) { redP[wid] = pP; redD[wid] = pD; }
    __syncthreads();
    if (tid == 0) {
        float P = 0.f, Dd = 0.f;
#pragma unroll
        for (int i = 0; i < 8; ++i) { P += redP[i]; Dd += redD[i]; }
        const int cta = blockIdx.y * G2_MTILES + blockIdx.x;
        g_P2[cta] = P;
        g_D2[cta] = Dd;
    }
}

// ---------------- finalize: out = K*S - (1+2K)*D, K = 0.1 ----------------
__global__ __launch_bounds__(32) void finalize_kernel(float* __restrict__ out)
{
    const int lane = threadIdx.x;
    float P = 0.f, Dd = 0.f;
    for (int i = lane; i < G2_CTAS; i += 32) { P += g_P2[i]; Dd += g_D2[i]; }
#pragma unroll
    for (int off = 16; off > 0; off >>= 1) {
        P  += __shfl_down_sync(0xffffffffu, P, off);
        Dd += __shfl_down_sync(0xffffffffu, Dd, off);
    }
    if (lane == 0) out[0] = 0.1f * P - 1.2f * Dd;
}

// ---------------- launch ----------------
extern "C" void kernel_launch(void* const* d_in, const int* in_sizes, int n_in,
                              void* d_out, int out_size)
{
    (void)in_sizes; (void)n_in; (void)out_size;
    const float* w_re  = (const float*)d_in[0];
    const float* w_im  = (const float*)d_in[1];
    const float* th_re = (const float*)d_in[2];
    const float* th_im = (const float*)d_in[3];
    const float* G_re  = (const float*)d_in[4];
    const float* G_im  = (const float*)d_in[5];
    const float* st_re = (const float*)d_in[6];
    const float* st_im = (const float*)d_in[7];
    const int* sweep   = (const int*)d_in[10];   // addw (d_in[8],[9]) unused: var term * 0.0

    conv_kernel<<<CONVA_BLOCKS + CONVB_BLOCKS + CONVW_BLOCKS, 256>>>(
        G_re, G_im, th_re, th_im, st_re, st_im, w_re, w_im);
    gemm_mma_kernel<<<dim3(ARR / MT, NPAD / NT, ZSPLIT), 256>>>();
    reduceBd_kernel<<<dim3(ARR / 32, NPAD / 32), 256>>>();
    gemm2_kernel<<<dim3(G2_MTILES, G2_NTILES), 256>>>(sweep);
    finalize_kernel<<<1, 32>>>((float*)d_out);
}